// round 2
// baseline (speedup 1.0000x reference)
#include <cuda_runtime.h>
#include <math_constants.h>

// Problem constants
#define B_    32
#define L_    1000
#define NCHAR 256
#define DM    512
#define NH    8
#define DH    64
#define XROWS (NCHAR + L_)   // 1256
#define LN10000 9.210340371976184f

// Scratch (device globals: no allocation allowed)
__device__ float g_X[XROWS * DM];          // [emb rows ; pe rows]
__device__ float g_T[2 * XROWS * DM];      // Tk, Tv tables (bias folded into pe rows)
__device__ float g_q[B_ * DM];             // per-batch query (single position)
__device__ float g_ctx[B_ * DM];           // attention output at last valid position

// ---------------------------------------------------------------------------
// Kernel 1: build X = [emb(256,512) ; pe(1000,512)]
// ---------------------------------------------------------------------------
__global__ void build_x_kernel(const float* __restrict__ emb) {
    int i = blockIdx.x * blockDim.x + threadIdx.x;
    if (i >= XROWS * DM) return;
    int r = i >> 9;       // /512
    int e = i & 511;
    float v;
    if (r < NCHAR) {
        v = emb[i];
    } else {
        int t = r - NCHAR;
        int pair = e >> 1;
        float div = expf((float)(2 * pair) * (-LN10000 / (float)DM));
        float ang = (float)t * div;
        v = (e & 1) ? cosf(ang) : sinf(ang);
    }
    g_X[i] = v;
}

// ---------------------------------------------------------------------------
// Kernel 2: T[z] = X @ W_z^T  (+ bias on pe rows).  z=0 -> K, z=1 -> V.
// Tiled 64x64, BK=16, 256 threads, 4x4 register blocking.
// ---------------------------------------------------------------------------
#define BM 64
#define BN 64
#define BK 16
__global__ void gemm_tables_kernel(const float* __restrict__ Wk,
                                   const float* __restrict__ Wv,
                                   const float* __restrict__ bk,
                                   const float* __restrict__ bv) {
    int z = blockIdx.z;
    const float* W    = (z == 0) ? Wk : Wv;
    const float* bias = (z == 0) ? bk : bv;
    float* out = g_T + (size_t)z * XROWS * DM;

    int m0 = blockIdx.y * BM;
    int n0 = blockIdx.x * BN;

    __shared__ float As[BK][BM + 4];
    __shared__ float Bs[BK][BN + 4];

    int tid  = threadIdx.x;          // 256
    int lrow = tid >> 2;             // 0..63
    int lcol = (tid & 3) * 4;        // 0,4,8,12
    int ty = tid >> 4;               // 0..15 (output row group)
    int tx = tid & 15;               // 0..15 (output col group)

    float acc[4][4] = {};

    for (int k0 = 0; k0 < DM; k0 += BK) {
        // Load A tile (64 x 16) from g_X
        int gr = m0 + lrow;
        float4 av = make_float4(0.f, 0.f, 0.f, 0.f);
        if (gr < XROWS)
            av = *(const float4*)(g_X + (size_t)gr * DM + k0 + lcol);
        As[lcol + 0][lrow] = av.x; As[lcol + 1][lrow] = av.y;
        As[lcol + 2][lrow] = av.z; As[lcol + 3][lrow] = av.w;

        // Load B tile (64 x 16) from W (row-major [512 out, 512 in])
        float4 bv4 = *(const float4*)(W + (size_t)(n0 + lrow) * DM + k0 + lcol);
        Bs[lcol + 0][lrow] = bv4.x; Bs[lcol + 1][lrow] = bv4.y;
        Bs[lcol + 2][lrow] = bv4.z; Bs[lcol + 3][lrow] = bv4.w;

        __syncthreads();

        #pragma unroll
        for (int kk = 0; kk < BK; kk++) {
            float4 a4 = *(const float4*)&As[kk][ty * 4];
            float4 b4 = *(const float4*)&Bs[kk][tx * 4];
            float a[4] = {a4.x, a4.y, a4.z, a4.w};
            float b[4] = {b4.x, b4.y, b4.z, b4.w};
            #pragma unroll
            for (int i = 0; i < 4; i++)
                #pragma unroll
                for (int j = 0; j < 4; j++)
                    acc[i][j] += a[i] * b[j];
        }
        __syncthreads();
    }

    #pragma unroll
    for (int i = 0; i < 4; i++) {
        int r = m0 + ty * 4 + i;
        if (r >= XROWS) continue;
        #pragma unroll
        for (int j = 0; j < 4; j++) {
            int c = n0 + tx * 4 + j;
            float v = acc[i][j];
            if (r >= NCHAR) v += bias[c];      // fold bias into pe rows
            out[(size_t)r * DM + c] = v;
        }
    }
}

// ---------------------------------------------------------------------------
// Kernel 3: q[b] = Wq @ (emb[c_p] + pe_p) + bq, one block per batch
// data / lengths are int32 (JAX x64-disabled downcasts int64 -> int32)
// ---------------------------------------------------------------------------
__global__ void q_kernel(const int* __restrict__ data,
                         const int* __restrict__ lengths,
                         const float* __restrict__ emb,
                         const float* __restrict__ Wq,
                         const float* __restrict__ bq) {
    int b = blockIdx.x;
    __shared__ float xs[DM];
    int p = lengths[b] - 1;
    if (p < 0) p = 0;
    if (p >= L_) p = L_ - 1;
    int c = data[(size_t)b * L_ + p];
    c &= (NCHAR - 1);                 // defensive (valid data unchanged)
    int tid = threadIdx.x;           // 512
    {
        int e = tid;
        int pair = e >> 1;
        float div = expf((float)(2 * pair) * (-LN10000 / (float)DM));
        float ang = (float)p * div;
        float pe = (e & 1) ? cosf(ang) : sinf(ang);
        xs[e] = emb[(size_t)c * DM + e] + pe;
    }
    __syncthreads();
    int w = tid >> 5, lane = tid & 31;
    for (int j = w * 32; j < w * 32 + 32; j++) {
        const float* wr = Wq + (size_t)j * DM;
        float s = 0.f;
        #pragma unroll 4
        for (int e = lane; e < DM; e += 32) s += wr[e] * xs[e];
        #pragma unroll
        for (int off = 16; off; off >>= 1) s += __shfl_xor_sync(0xffffffffu, s, off);
        if (lane == 0) g_q[b * DM + j] = s + bq[j];
    }
}

// ---------------------------------------------------------------------------
// Kernel 4: single-row causal attention per (head, batch).
// 8 warps, each runs an online softmax over strided positions; warp-merge.
// ---------------------------------------------------------------------------
__global__ void attn_kernel(const int* __restrict__ data,
                            const int* __restrict__ lengths) {
    int h = blockIdx.x;
    int b = blockIdx.y;
    __shared__ int   chars[L_];
    __shared__ float sm[8], sl[8];
    __shared__ float sacc[8][DH];

    int tid = threadIdx.x;           // 256
    int count = lengths[b];          // attend keys 0..count-1
    if (count < 1) count = 1;
    if (count > L_) count = L_;
    for (int t = tid; t < count; t += 256)
        chars[t] = data[(size_t)b * L_ + t] & (NCHAR - 1);
    __syncthreads();

    int w = tid >> 5, lane = tid & 31;
    const float* Tk = g_T;
    const float* Tv = g_T + (size_t)XROWS * DM;

    float2 q2 = *(const float2*)(g_q + b * DM + h * DH + 2 * lane);

    float m = -CUDART_INF_F, l = 0.f;
    float accx = 0.f, accy = 0.f;

    for (int t = w; t < count; t += 8) {
        int c = chars[t];
        const float* kerow = Tk + (size_t)c * DM + h * DH;
        const float* kprow = Tk + (size_t)(NCHAR + t) * DM + h * DH;
        float2 ke = *((const float2*)kerow + lane);
        float2 kp = *((const float2*)kprow + lane);
        float kx = ke.x + kp.x, ky = ke.y + kp.y;
        float part = q2.x * kx + q2.y * ky;
        #pragma unroll
        for (int off = 16; off; off >>= 1)
            part += __shfl_xor_sync(0xffffffffu, part, off);
        float s = part * 0.125f;     // 1/sqrt(64)

        float m_new = fmaxf(m, s);
        float alpha = __expf(m - m_new);
        float wgt   = __expf(s - m_new);

        const float* verow = Tv + (size_t)c * DM + h * DH;
        const float* vprow = Tv + (size_t)(NCHAR + t) * DM + h * DH;
        float2 ve = *((const float2*)verow + lane);
        float2 vp = *((const float2*)vprow + lane);

        l    = l * alpha + wgt;
        accx = accx * alpha + wgt * (ve.x + vp.x);
        accy = accy * alpha + wgt * (ve.y + vp.y);
        m = m_new;
    }

    sacc[w][2 * lane]     = accx;
    sacc[w][2 * lane + 1] = accy;
    if (lane == 0) { sm[w] = m; sl[w] = l; }
    __syncthreads();

    if (tid < DH) {
        float M = -CUDART_INF_F;
        #pragma unroll
        for (int i = 0; i < 8; i++) M = fmaxf(M, sm[i]);
        float Lsum = 0.f, num = 0.f;
        #pragma unroll
        for (int i = 0; i < 8; i++) {
            float f = __expf(sm[i] - M);
            Lsum += sl[i] * f;
            num  += sacc[i][tid] * f;
        }
        g_ctx[b * DM + h * DH + tid] = num / Lsum;
    }
}

// ---------------------------------------------------------------------------
// Kernel 5: prediction head. h = lrelu(ctx@W1^T+b1); out = mean(relu(h@W2^T+b2)); lrelu
// ---------------------------------------------------------------------------
__global__ void mlp_kernel(const float* __restrict__ W1,
                           const float* __restrict__ b1,
                           const float* __restrict__ W2,
                           const float* __restrict__ b2,
                           float* __restrict__ out) {
    int b = blockIdx.x;
    __shared__ float xs[DM], hs[DM], o8[8];
    int tid = threadIdx.x;           // 512
    xs[tid] = g_ctx[b * DM + tid];
    __syncthreads();
    int w = tid >> 5, lane = tid & 31;
    for (int j = w * 32; j < w * 32 + 32; j++) {
        const float* wr = W1 + (size_t)j * DM;
        float s = 0.f;
        #pragma unroll 4
        for (int e = lane; e < DM; e += 32) s += wr[e] * xs[e];
        #pragma unroll
        for (int off = 16; off; off >>= 1) s += __shfl_xor_sync(0xffffffffu, s, off);
        if (lane == 0) {
            float v = s + b1[j];
            hs[j] = (v > 0.f) ? v : 0.01f * v;      // leaky_relu
        }
    }
    __syncthreads();
    if (w < 8) {
        const float* wr = W2 + (size_t)w * DM;
        float s = 0.f;
        #pragma unroll 4
        for (int e = lane; e < DM; e += 32) s += wr[e] * hs[e];
        #pragma unroll
        for (int off = 16; off; off >>= 1) s += __shfl_xor_sync(0xffffffffu, s, off);
        if (lane == 0) {
            float v = s + b2[w];
            o8[w] = (v > 0.f) ? v : 0.f;            // relu
        }
    }
    __syncthreads();
    if (tid == 0) {
        float mv = 0.f;
        #pragma unroll
        for (int i = 0; i < 8; i++) mv += o8[i];
        mv *= 0.125f;                                // mean over 8
        out[b] = (mv > 0.f) ? mv : 0.01f * mv;       // final leaky_relu
    }
}

// ---------------------------------------------------------------------------
extern "C" void kernel_launch(void* const* d_in, const int* in_sizes, int n_in,
                              void* d_out, int out_size) {
    const int* data    = (const int*)d_in[0];    // int32 (JAX x64 disabled)
    const int* lengths = (const int*)d_in[1];
    const float* emb = (const float*)d_in[2];
    const float* Wq  = (const float*)d_in[3];
    const float* bq  = (const float*)d_in[4];
    const float* Wk  = (const float*)d_in[5];
    const float* bk  = (const float*)d_in[6];
    const float* Wv  = (const float*)d_in[7];
    const float* bv  = (const float*)d_in[8];
    const float* W1  = (const float*)d_in[9];
    const float* b1  = (const float*)d_in[10];
    const float* W2  = (const float*)d_in[11];
    const float* b2  = (const float*)d_in[12];
    float* out = (float*)d_out;

    // 1) X = [emb ; pe]
    build_x_kernel<<<(XROWS * DM + 255) / 256, 256>>>(emb);
    // 2) Tk/Tv tables: [1256,512] @ [512,512]^T x2
    dim3 ggrid(DM / BN, (XROWS + BM - 1) / BM, 2);
    gemm_tables_kernel<<<ggrid, 256>>>(Wk, Wv, bk, bv);
    // 3) per-batch query at last valid position
    q_kernel<<<B_, DM>>>(data, lengths, emb, Wq, bq);
    // 4) single-row attention per (head, batch)
    attn_kernel<<<dim3(NH, B_), 256>>>(data, lengths);
    // 5) prediction head
    mlp_kernel<<<B_, DM>>>(W1, b1, W2, b2, out);
}

// round 3
// speedup vs baseline: 1.0203x; 1.0203x over previous
#include <cuda_runtime.h>
#include <math_constants.h>

// Problem constants
#define B_    32
#define L_    1000
#define NCHAR 256
#define DM    512
#define NH    8
#define DH    64
#define XROWS (NCHAR + L_)   // 1256
#define LN10000 9.210340371976184f

// Scratch (device globals: no allocation allowed)
__device__ float g_X[XROWS * DM];          // [emb rows ; pe rows]
__device__ float g_T[2 * XROWS * DM];      // Tk, Tv tables (bias folded into pe rows)
__device__ float g_q[B_ * DM];             // per-batch query (single position)
__device__ float g_ctx[B_ * DM];           // attention output at last valid position
__device__ float g_dot[NH * B_ * XROWS];   // D[h][b][r] = q[b,h] . Tk[r,h]
__device__ float g_wr [NH * B_ * XROWS];   // WR[h][b][r] softmax weight rows (char bins + pos)

// ---------------------------------------------------------------------------
// Kernel 1: build X = [emb(256,512) ; pe(1000,512)]
// ---------------------------------------------------------------------------
__global__ void build_x_kernel(const float* __restrict__ emb) {
    int i = blockIdx.x * blockDim.x + threadIdx.x;
    if (i >= XROWS * DM) return;
    int r = i >> 9;       // /512
    int e = i & 511;
    float v;
    if (r < NCHAR) {
        v = emb[i];
    } else {
        int t = r - NCHAR;
        int pair = e >> 1;
        float div = expf((float)(2 * pair) * (-LN10000 / (float)DM));
        float ang = (float)t * div;
        v = (e & 1) ? cosf(ang) : sinf(ang);
    }
    g_X[i] = v;
}

// ---------------------------------------------------------------------------
// Kernel 2: T[z] = X @ W_z^T  (+ bias on pe rows).  z=0 -> K, z=1 -> V.
// ---------------------------------------------------------------------------
#define BM 64
#define BN 64
#define BK 16
__global__ void gemm_tables_kernel(const float* __restrict__ Wk,
                                   const float* __restrict__ Wv,
                                   const float* __restrict__ bk,
                                   const float* __restrict__ bv) {
    int z = blockIdx.z;
    const float* W    = (z == 0) ? Wk : Wv;
    const float* bias = (z == 0) ? bk : bv;
    float* out = g_T + (size_t)z * XROWS * DM;

    int m0 = blockIdx.y * BM;
    int n0 = blockIdx.x * BN;

    __shared__ float As[BK][BM + 4];
    __shared__ float Bs[BK][BN + 4];

    int tid  = threadIdx.x;          // 256
    int lrow = tid >> 2;             // 0..63
    int lcol = (tid & 3) * 4;        // 0,4,8,12
    int ty = tid >> 4;               // 0..15
    int tx = tid & 15;               // 0..15

    float acc[4][4] = {};

    for (int k0 = 0; k0 < DM; k0 += BK) {
        int gr = m0 + lrow;
        float4 av = make_float4(0.f, 0.f, 0.f, 0.f);
        if (gr < XROWS)
            av = *(const float4*)(g_X + (size_t)gr * DM + k0 + lcol);
        As[lcol + 0][lrow] = av.x; As[lcol + 1][lrow] = av.y;
        As[lcol + 2][lrow] = av.z; As[lcol + 3][lrow] = av.w;

        float4 bv4 = *(const float4*)(W + (size_t)(n0 + lrow) * DM + k0 + lcol);
        Bs[lcol + 0][lrow] = bv4.x; Bs[lcol + 1][lrow] = bv4.y;
        Bs[lcol + 2][lrow] = bv4.z; Bs[lcol + 3][lrow] = bv4.w;

        __syncthreads();

        #pragma unroll
        for (int kk = 0; kk < BK; kk++) {
            float4 a4 = *(const float4*)&As[kk][ty * 4];
            float4 b4 = *(const float4*)&Bs[kk][tx * 4];
            float a[4] = {a4.x, a4.y, a4.z, a4.w};
            float b[4] = {b4.x, b4.y, b4.z, b4.w};
            #pragma unroll
            for (int i = 0; i < 4; i++)
                #pragma unroll
                for (int j = 0; j < 4; j++)
                    acc[i][j] += a[i] * b[j];
        }
        __syncthreads();
    }

    #pragma unroll
    for (int i = 0; i < 4; i++) {
        int r = m0 + ty * 4 + i;
        if (r >= XROWS) continue;
        #pragma unroll
        for (int j = 0; j < 4; j++) {
            int c = n0 + tx * 4 + j;
            float v = acc[i][j];
            if (r >= NCHAR) v += bias[c];
            out[(size_t)r * DM + c] = v;
        }
    }
}

// ---------------------------------------------------------------------------
// Kernel 3: q[b] = Wq @ (emb[c_p] + pe_p) + bq
// ---------------------------------------------------------------------------
__global__ void q_kernel(const int* __restrict__ data,
                         const int* __restrict__ lengths,
                         const float* __restrict__ emb,
                         const float* __restrict__ Wq,
                         const float* __restrict__ bq) {
    int b = blockIdx.x;
    __shared__ float xs[DM];
    int p = lengths[b] - 1;
    if (p < 0) p = 0;
    if (p >= L_) p = L_ - 1;
    int c = data[(size_t)b * L_ + p] & (NCHAR - 1);
    int tid = threadIdx.x;           // 512
    {
        int e = tid;
        int pair = e >> 1;
        float div = expf((float)(2 * pair) * (-LN10000 / (float)DM));
        float ang = (float)p * div;
        float pe = (e & 1) ? cosf(ang) : sinf(ang);
        xs[e] = emb[(size_t)c * DM + e] + pe;
    }
    __syncthreads();
    int w = tid >> 5, lane = tid & 31;
    for (int j = w * 32; j < w * 32 + 32; j++) {
        const float* wr = Wq + (size_t)j * DM;
        float s = 0.f;
        #pragma unroll 4
        for (int e = lane; e < DM; e += 32) s += wr[e] * xs[e];
        #pragma unroll
        for (int off = 16; off; off >>= 1) s += __shfl_xor_sync(0xffffffffu, s, off);
        if (lane == 0) g_q[b * DM + j] = s + bq[j];
    }
}

// ---------------------------------------------------------------------------
// Kernel 4a: D[h][b][r] = q[b,h] . Tk[r,h]  for all 1256 table rows.
// grid (NH, ceil(XROWS/64)), 256 threads. Thread owns (b, 8 consecutive r).
// ---------------------------------------------------------------------------
#define RT 64
__global__ void dots_kernel() {
    int h  = blockIdx.x;
    int r0 = blockIdx.y * RT;
    __shared__ float Qs[B_][DH + 1];
    __shared__ float Tks[DH][RT + 4];   // transposed [d][r], row stride 68 (16B aligned)
    int tid = threadIdx.x;

    for (int i = tid; i < B_ * DH; i += 256) {
        int b = i >> 6, d = i & 63;
        Qs[b][d] = g_q[b * DM + h * DH + d];
    }
    for (int i = tid * 4; i < RT * DH; i += 1024) {
        int r = i >> 6, d = i & 63;
        int gr = r0 + r;
        float4 v = make_float4(0.f, 0.f, 0.f, 0.f);
        if (gr < XROWS) v = *(const float4*)(g_T + (size_t)gr * DM + h * DH + d);
        Tks[d + 0][r] = v.x; Tks[d + 1][r] = v.y;
        Tks[d + 2][r] = v.z; Tks[d + 3][r] = v.w;
    }
    __syncthreads();

    int b  = tid >> 3;           // 0..31
    int rg = (tid & 7) * 8;      // 0..56
    float acc[8] = {};
    #pragma unroll 8
    for (int d = 0; d < DH; d++) {
        float qv = Qs[b][d];
        float4 t0 = *(const float4*)&Tks[d][rg];
        float4 t1 = *(const float4*)&Tks[d][rg + 4];
        acc[0] += qv * t0.x; acc[1] += qv * t0.y;
        acc[2] += qv * t0.z; acc[3] += qv * t0.w;
        acc[4] += qv * t1.x; acc[5] += qv * t1.y;
        acc[6] += qv * t1.z; acc[7] += qv * t1.w;
    }
    if (r0 + rg < XROWS) {       // XROWS % 8 == 0: octet fully valid or fully out
        float* Drow = g_dot + (size_t)(h * B_ + b) * XROWS + r0 + rg;
        *(float4*)(Drow)     = make_float4(acc[0], acc[1], acc[2], acc[3]);
        *(float4*)(Drow + 4) = make_float4(acc[4], acc[5], acc[6], acc[7]);
    }
}

// ---------------------------------------------------------------------------
// Kernel 4b: per (b,h) softmax over valid positions + char binning.
// WR[h][b][c]      = sum of weights of positions with char c   (c < 256)
// WR[h][b][256+t]  = weight of position t (0 if t >= count)
// ---------------------------------------------------------------------------
__global__ void softmax_bin_kernel(const int* __restrict__ data,
                                   const int* __restrict__ lengths) {
    int h = blockIdx.x;
    int b = blockIdx.y;
    __shared__ float s[L_];
    __shared__ float bins[NCHAR];
    __shared__ float red[8];

    int tid = threadIdx.x;       // 256
    int count = lengths[b];
    if (count < 1) count = 1;
    if (count > L_) count = L_;

    const float* D = g_dot + (size_t)(h * B_ + b) * XROWS;

    float lm = -CUDART_INF_F;
    for (int t = tid; t < count; t += 256) {
        int c = data[(size_t)b * L_ + t] & (NCHAR - 1);
        float v = (D[NCHAR + t] + D[c]) * 0.125f;   // 1/sqrt(64)
        s[t] = v;
        lm = fmaxf(lm, v);
    }
    // block max
    #pragma unroll
    for (int off = 16; off; off >>= 1) lm = fmaxf(lm, __shfl_xor_sync(0xffffffffu, lm, off));
    if ((tid & 31) == 0) red[tid >> 5] = lm;
    __syncthreads();
    float M = -CUDART_INF_F;
    #pragma unroll
    for (int i = 0; i < 8; i++) M = fmaxf(M, red[i]);
    __syncthreads();

    float ls = 0.f;
    for (int t = tid; t < count; t += 256) {
        float e = __expf(s[t] - M);
        s[t] = e;
        ls += e;
    }
    #pragma unroll
    for (int off = 16; off; off >>= 1) ls += __shfl_xor_sync(0xffffffffu, ls, off);
    if ((tid & 31) == 0) red[tid >> 5] = ls;
    bins[tid] = 0.f;             // tid covers 0..255 == NCHAR
    __syncthreads();
    float S = 0.f;
    #pragma unroll
    for (int i = 0; i < 8; i++) S += red[i];
    float inv = 1.f / S;

    float* WR = g_wr + (size_t)(h * B_ + b) * XROWS;
    for (int t = tid; t < L_; t += 256) {
        float w = 0.f;
        if (t < count) {
            w = s[t] * inv;
            atomicAdd(&bins[data[(size_t)b * L_ + t] & (NCHAR - 1)], w);
        }
        WR[NCHAR + t] = w;
    }
    __syncthreads();
    WR[tid] = bins[tid];
}

// ---------------------------------------------------------------------------
// Kernel 4c: ctx[b, h*64 + d] = sum_r WR[h][b][r] * Tv[r][h][d]
// grid (NH, 4): each block does a 16-wide d-quarter for all 32 b.
// Thread owns (b, 2 consecutive d).
// ---------------------------------------------------------------------------
#define CT 64
__global__ void ctx_kernel() {
    int h  = blockIdx.x;
    int dq = blockIdx.y * 16;            // d-quarter base within head
    __shared__ float Tvs[CT][20];        // [r][16 d + pad4], row 80B (16B aligned)
    __shared__ float WRs[B_][CT + 4];    // row stride 68 floats (16B aligned)

    const float* Tv = g_T + (size_t)XROWS * DM;
    int tid = threadIdx.x;               // 256
    int b  = tid >> 3;                   // 0..31
    int dp = (tid & 7) * 2;              // 0..14

    float acc0 = 0.f, acc1 = 0.f;

    for (int r0 = 0; r0 < XROWS; r0 += CT) {
        // Tv tile: 64 r x 16 d = 1024 floats -> 1 float4 per thread
        {
            int i = tid * 4;             // < 4096? only need 1024
            if (i < CT * 16) {
                int r = i >> 4, d = i & 15;
                int gr = r0 + r;
                float4 v = make_float4(0.f, 0.f, 0.f, 0.f);
                if (gr < XROWS)
                    v = *(const float4*)(Tv + (size_t)gr * DM + h * DH + dq + d);
                *(float4*)&Tvs[r][d] = v;
            }
        }
        // WR tile: 32 b x 64 r = 2048 floats -> 2 float4 per thread
        for (int i = tid * 4; i < B_ * CT; i += 1024) {
            int bb = i >> 6, r = i & 63;
            int gr = r0 + r;
            float4 v = make_float4(0.f, 0.f, 0.f, 0.f);
            if (gr < XROWS)              // XROWS % 4 == 0: float4 fully valid or out
                v = *(const float4*)(g_wr + (size_t)(h * B_ + bb) * XROWS + gr);
            *(float4*)&WRs[bb][r] = v;
        }
        __syncthreads();

        #pragma unroll 8
        for (int rr = 0; rr < CT; rr++) {
            float w = WRs[b][rr];
            float2 tv = *(const float2*)&Tvs[rr][dp];
            acc0 += w * tv.x;
            acc1 += w * tv.y;
        }
        __syncthreads();
    }

    *(float2*)(g_ctx + b * DM + h * DH + dq + dp) = make_float2(acc0, acc1);
}

// ---------------------------------------------------------------------------
// Kernel 5: prediction head
// ---------------------------------------------------------------------------
__global__ void mlp_kernel(const float* __restrict__ W1,
                           const float* __restrict__ b1,
                           const float* __restrict__ W2,
                           const float* __restrict__ b2,
                           float* __restrict__ out) {
    int b = blockIdx.x;
    __shared__ float xs[DM], hs[DM], o8[8];
    int tid = threadIdx.x;           // 512
    xs[tid] = g_ctx[b * DM + tid];
    __syncthreads();
    int w = tid >> 5, lane = tid & 31;
    for (int j = w * 32; j < w * 32 + 32; j++) {
        const float* wr = W1 + (size_t)j * DM;
        float s = 0.f;
        #pragma unroll 4
        for (int e = lane; e < DM; e += 32) s += wr[e] * xs[e];
        #pragma unroll
        for (int off = 16; off; off >>= 1) s += __shfl_xor_sync(0xffffffffu, s, off);
        if (lane == 0) {
            float v = s + b1[j];
            hs[j] = (v > 0.f) ? v : 0.01f * v;
        }
    }
    __syncthreads();
    if (w < 8) {
        const float* wr = W2 + (size_t)w * DM;
        float s = 0.f;
        #pragma unroll 4
        for (int e = lane; e < DM; e += 32) s += wr[e] * hs[e];
        #pragma unroll
        for (int off = 16; off; off >>= 1) s += __shfl_xor_sync(0xffffffffu, s, off);
        if (lane == 0) {
            float v = s + b2[w];
            o8[w] = (v > 0.f) ? v : 0.f;
        }
    }
    __syncthreads();
    if (tid == 0) {
        float mv = 0.f;
        #pragma unroll
        for (int i = 0; i < 8; i++) mv += o8[i];
        mv *= 0.125f;
        out[b] = (mv > 0.f) ? mv : 0.01f * mv;
    }
}

// ---------------------------------------------------------------------------
extern "C" void kernel_launch(void* const* d_in, const int* in_sizes, int n_in,
                              void* d_out, int out_size) {
    const int* data    = (const int*)d_in[0];    // int32 (JAX x64 disabled)
    const int* lengths = (const int*)d_in[1];
    const float* emb = (const float*)d_in[2];
    const float* Wq  = (const float*)d_in[3];
    const float* bq  = (const float*)d_in[4];
    const float* Wk  = (const float*)d_in[5];
    const float* bk  = (const float*)d_in[6];
    const float* Wv  = (const float*)d_in[7];
    const float* bv  = (const float*)d_in[8];
    const float* W1  = (const float*)d_in[9];
    const float* b1  = (const float*)d_in[10];
    const float* W2  = (const float*)d_in[11];
    const float* b2  = (const float*)d_in[12];
    float* out = (float*)d_out;

    build_x_kernel<<<(XROWS * DM + 255) / 256, 256>>>(emb);
    dim3 ggrid(DM / BN, (XROWS + BM - 1) / BM, 2);
    gemm_tables_kernel<<<ggrid, 256>>>(Wk, Wv, bk, bv);
    q_kernel<<<B_, DM>>>(data, lengths, emb, Wq, bq);
    dots_kernel<<<dim3(NH, (XROWS + RT - 1) / RT), 256>>>();
    softmax_bin_kernel<<<dim3(NH, B_), 256>>>(data, lengths);
    ctx_kernel<<<dim3(NH, 4), 256>>>();
    mlp_kernel<<<B_, DM>>>(W1, b1, W2, b2, out);
}